// round 10
// baseline (speedup 1.0000x reference)
#include <cuda_runtime.h>
#include <cuda_bf16.h>
#include <math.h>

#define BB 64
#define SS 1024
#define II 256
#define HH 512
#define OO 256
#define G4 2048
#define NCTA 32

// step-kernel smem map (bytes): padded tiles [64 rows][520 bf16], pitch 1040B
#define TPITCH 1040
#define SM_WLO 0
#define SM_HHI 66560
#define SM_HLO 133120
#define SM_GB  199680
#define SM_TOTAL 216832
#define GBP 66            // gbuf pitch (floats)

__device__ __forceinline__ float fsigmoid(float x){ return __fdividef(1.0f, 1.0f + __expf(-x)); }
__device__ __forceinline__ float ftanh(float x){ return 1.0f - 2.0f*__fdividef(1.0f, __expf(2.0f*x)+1.0f); }
__device__ __forceinline__ unsigned long long pack2(float lo, float hi) {
    unsigned long long r; asm("mov.b64 %0, {%1, %2};" : "=l"(r) : "f"(lo), "f"(hi)); return r;
}
__device__ __forceinline__ unsigned long long ffma2(unsigned long long a, unsigned long long b, unsigned long long c) {
    unsigned long long d; asm("fma.rn.f32x2 %0, %1, %2, %3;" : "=l"(d) : "l"(a), "l"(b), "l"(c)); return d;
}
__device__ __forceinline__ float2 unpack2(unsigned long long v) {
    float2 f; asm("mov.b64 {%0, %1}, %2;" : "=f"(f.x), "=f"(f.y) : "l"(v)); return f;
}
__device__ __forceinline__ unsigned smem_u32(const void* p) {
    unsigned a;
    asm("{.reg .u64 t; cvta.to.shared.u64 t, %1; cvt.u32.u64 %0, t;}" : "=r"(a) : "l"(p));
    return a;
}
__device__ __forceinline__ void ldsm4(unsigned& r0, unsigned& r1, unsigned& r2, unsigned& r3,
                                      unsigned addr) {
    asm volatile("ldmatrix.sync.aligned.m8n8.x4.shared.b16 {%0,%1,%2,%3}, [%4];"
                 : "=r"(r0), "=r"(r1), "=r"(r2), "=r"(r3) : "r"(addr));
}
__device__ __forceinline__ void mma16816(float& c0, float& c1, float& c2, float& c3,
                                         unsigned a0, unsigned a1, unsigned a2, unsigned a3,
                                         unsigned b0, unsigned b1) {
    asm volatile(
        "mma.sync.aligned.m16n8k16.row.col.f32.bf16.bf16.f32 "
        "{%0,%1,%2,%3},{%4,%5,%6,%7},{%8,%9},{%0,%1,%2,%3};"
        : "+f"(c0), "+f"(c1), "+f"(c2), "+f"(c3)
        : "r"(a0), "r"(a1), "r"(a2), "r"(a3), "r"(b0), "r"(b1));
}

// ---------------- device scratch ----------------
__device__ float g_gx[(size_t)SS * BB * G4];               // [s][b][col]
__device__ __align__(16) __nv_bfloat16 g_whi[NCTA][64 * 512];   // [cta][row][k]
__device__ __align__(16) __nv_bfloat16 g_wlo[NCTA][64 * 512];
__device__ __align__(16) __nv_bfloat16 g_h[2][2][BB * HH];      // [par][hi/lo][b][k]
__device__ float g_hfin[BB * HH];
__device__ unsigned g_bar_cnt, g_bar_gen;

// ---------------- init ----------------
__global__ void __launch_bounds__(256) init_kernel() {
    int t = blockIdx.x * 256 + threadIdx.x;
    if (t < 16384) ((uint4*)g_h)[t] = make_uint4(0,0,0,0);
    if (t == 0) { g_bar_cnt = 0u; g_bar_gen = 0u; }
}

// ---------------- W prep: bf16 hi/lo split, plain [row][k] tiles ----------
__global__ void __launch_bounds__(256) prepw_kernel(
    const float* __restrict__ Wf, const float* __restrict__ Wi,
    const float* __restrict__ Wc, const float* __restrict__ Wo)
{
    int gid = blockIdx.x * 256 + threadIdx.x;    // 32*64*256 = 524288
    int cta = gid >> 14;
    int rem = gid & 16383;
    int r   = rem >> 8;           // gate row within CTA: g*16 + l
    int kp  = rem & 255;
    int k0  = kp * 2;
    int g = r >> 4, l = r & 15, j = cta * 16 + l;
    const float* W = (g==0)?Wf:(g==1)?Wi:(g==2)?Wc:Wo;
    #pragma unroll
    for (int q = 0; q < 2; q++) {
        int k = k0 + q;
        float w = W[(size_t)(II + k) * HH + j];
        __nv_bfloat16 hi = __float2bfloat16(w);
        __nv_bfloat16 lo = __float2bfloat16(w - __bfloat162float(hi));
        g_whi[cta][r * 512 + k] = hi;
        g_wlo[cta][r * 512 + k] = lo;
    }
}

// ---------------- input projection (unchanged, passing) ----------------
__global__ void __launch_bounds__(256) precompute_kernel(
    const float* __restrict__ x,
    const float* __restrict__ Wf, const float* __restrict__ Wi,
    const float* __restrict__ Wc, const float* __restrict__ Wo,
    const float* __restrict__ bf, const float* __restrict__ bi,
    const float* __restrict__ bc, const float* __restrict__ bo)
{
    __shared__ float As[16][64], Bs[16][64];
    const int b = blockIdx.z, s0 = blockIdx.y * 64, c0 = blockIdx.x * 64;
    const int g = c0 >> 9, j0 = c0 & 511;
    const float* W    = (g==0)?Wf:(g==1)?Wi:(g==2)?Wc:Wo;
    const float* bias = (g==0)?bf:(g==1)?bi:(g==2)?bc:bo;
    const int t = threadIdx.x, tx = t & 15, ty = t >> 4;
    unsigned long long acc[4][2] = {};
    const int sr = t >> 2, kq = (t & 3) * 4;
    for (int k0 = 0; k0 < II; k0 += 16) {
        float4 av = *(const float4*)&x[((size_t)b * SS + s0 + sr) * II + k0 + kq];
        As[kq+0][sr]=av.x; As[kq+1][sr]=av.y; As[kq+2][sr]=av.z; As[kq+3][sr]=av.w;
        #pragma unroll
        for (int i = 0; i < 4; i++) {
            int e = t + i * 256, kk = e >> 6, nn = e & 63;
            Bs[kk][nn] = W[(size_t)(k0 + kk) * HH + j0 + nn];
        }
        __syncthreads();
        #pragma unroll
        for (int k = 0; k < 16; k++) {
            float4 a = *(const float4*)&As[k][ty * 4];
            ulonglong2 w = *(const ulonglong2*)&Bs[k][tx * 4];
            unsigned long long aa;
            aa = pack2(a.x, a.x); acc[0][0]=ffma2(aa,w.x,acc[0][0]); acc[0][1]=ffma2(aa,w.y,acc[0][1]);
            aa = pack2(a.y, a.y); acc[1][0]=ffma2(aa,w.x,acc[1][0]); acc[1][1]=ffma2(aa,w.y,acc[1][1]);
            aa = pack2(a.z, a.z); acc[2][0]=ffma2(aa,w.x,acc[2][0]); acc[2][1]=ffma2(aa,w.y,acc[2][1]);
            aa = pack2(a.w, a.w); acc[3][0]=ffma2(aa,w.x,acc[3][0]); acc[3][1]=ffma2(aa,w.y,acc[3][1]);
        }
        __syncthreads();
    }
    float4 bv = *(const float4*)&bias[j0 + tx * 4];
    #pragma unroll
    for (int mi = 0; mi < 4; mi++) {
        int s = s0 + ty * 4 + mi;
        float2 q0 = unpack2(acc[mi][0]), q1 = unpack2(acc[mi][1]);
        float4 v; v.x=q0.x+bv.x; v.y=q0.y+bv.y; v.z=q1.x+bv.z; v.w=q1.y+bv.w;
        *(float4*)&g_gx[((size_t)s * BB + b) * G4 + c0 + tx * 4] = v;
    }
}

// ---------------- persistent mma.sync step kernel ----------------
// CTA owns gate rows {g*16+l} -> h cols cta*16..+15.
// D[64,64] = W[64,512] @ h^T via m16n8k16 bf16, 3-pass split.
// Warp w: rows m0=16*(w&3), cols n0=32*(w>>2). W-hi frags in registers.
__global__ void __launch_bounds__(256, 1) step_kernel() {
    extern __shared__ __align__(16) unsigned char sm[];
    const int cta = blockIdx.x, t = threadIdx.x;
    const int wid = t >> 5, lane = t & 31;
    const int g8 = lane >> 2, t4 = lane & 3;
    const int m0 = (wid & 3) * 16, n0 = (wid >> 2) * 32;

    // --- W-lo tile -> smem once (64 rows x 1024B payload, pitch 1040) ---
    {
        const uint4* src = (const uint4*)g_wlo[cta];
        #pragma unroll
        for (int i = 0; i < 16; i++) {
            int ch = i * 256 + t;                 // 4096 chunks of 16B
            int r = ch >> 6, cc = ch & 63;
            *(uint4*)(sm + SM_WLO + r * TPITCH + cc * 16) = src[ch];
        }
    }
    // --- W-hi fragments -> registers once (strided gmem, init only) ---
    unsigned whi[128];
    {
        const __nv_bfloat16* wp = g_whi[cta];
        #pragma unroll
        for (int kb = 0; kb < 32; kb++) {
            whi[kb*4+0] = *(const unsigned*)&wp[(m0 + g8    ) * 512 + kb*16 + 2*t4    ];
            whi[kb*4+1] = *(const unsigned*)&wp[(m0 + g8 + 8) * 512 + kb*16 + 2*t4    ];
            whi[kb*4+2] = *(const unsigned*)&wp[(m0 + g8    ) * 512 + kb*16 + 2*t4 + 8];
            whi[kb*4+3] = *(const unsigned*)&wp[(m0 + g8 + 8) * 512 + kb*16 + 2*t4 + 8];
        }
    }
    __syncthreads();

    // ldmatrix lane base addresses (within-tile byte offsets)
    // B (h tiles, non-trans x4): rows n, matrices (n0..7,k0-7)(n0..7,k8-15)(n8..15,k0-7)(n8..15,k8-15)
    const int brow = ((lane & 16) >> 1) + (lane & 7);     // +0..7 / +8..15
    const unsigned boff = (unsigned)(brow * TPITCH + ((lane & 8) ? 16 : 0));
    const unsigned bhi_a = smem_u32(sm + SM_HHI) + boff + (unsigned)(n0 * TPITCH);
    const unsigned bhi_b = bhi_a + 16u * TPITCH;
    const unsigned blo_a = smem_u32(sm + SM_HLO) + boff + (unsigned)(n0 * TPITCH);
    const unsigned blo_b = blo_a + 16u * TPITCH;
    // A-lo (W-lo tile, non-trans x4): rows m, matrices (m0-7,k0-7)(m8-15,k0-7)(m0-7,k8-15)(m8-15,k8-15)
    const unsigned aoff = (unsigned)((m0 + (lane & 15)) * TPITCH + ((lane & 16) ? 16 : 0));
    const unsigned alo_b = smem_u32(sm + SM_WLO) + aoff;

    const int ub = t >> 2, lgrp = (t & 3) * 4;    // update cell (batch, 4 h-cols)
    float c_reg[4] = {};
    float* gb = (float*)(sm + SM_GB);

    for (int s = 0; s < SS; s++) {
        const int par = s & 1;

        // ---- stage h hi+lo into padded tiles (proven __ldcg+sync pattern) ----
        {
            const uint4* hs0 = (const uint4*)g_h[par][0];
            const uint4* hs1 = (const uint4*)g_h[par][1];
            #pragma unroll
            for (int i = 0; i < 16; i++) {
                int ch = i * 256 + t;
                int r = ch >> 6, cc = ch & 63;
                *(uint4*)(sm + SM_HHI + r * TPITCH + cc * 16) = __ldcg(hs0 + ch);
                *(uint4*)(sm + SM_HLO + r * TPITCH + cc * 16) = __ldcg(hs1 + ch);
            }
        }
        // prefetch Gx for this thread's cells
        float4 gx0, gx1, gx2, gx3;
        {
            const float* p = &g_gx[((size_t)s * BB + ub) * G4 + cta * 16 + lgrp];
            gx0 = *(const float4*)&p[0];
            gx1 = *(const float4*)&p[512];
            gx2 = *(const float4*)&p[1024];
            gx3 = *(const float4*)&p[1536];
        }
        __syncthreads();

        // ---- GEMM: 32 k-blocks x (5 LDSM.x4 + 12 MMA) ----
        float acc[4][4] = {};
        #pragma unroll
        for (int kb = 0; kb < 32; kb++) {
            const unsigned ko = (unsigned)(kb * 32);
            unsigned bh[8], bl[8], al[4];
            ldsm4(bh[0], bh[1], bh[2], bh[3], bhi_a + ko);
            ldsm4(bh[4], bh[5], bh[6], bh[7], bhi_b + ko);
            ldsm4(bl[0], bl[1], bl[2], bl[3], blo_a + ko);
            ldsm4(bl[4], bl[5], bl[6], bl[7], blo_b + ko);
            ldsm4(al[0], al[1], al[2], al[3], alo_b + ko);
            const unsigned a0 = whi[kb*4], a1 = whi[kb*4+1], a2 = whi[kb*4+2], a3 = whi[kb*4+3];
            #pragma unroll
            for (int nb = 0; nb < 4; nb++) {
                mma16816(acc[nb][0], acc[nb][1], acc[nb][2], acc[nb][3],
                         a0, a1, a2, a3, bh[nb*2], bh[nb*2+1]);
                mma16816(acc[nb][0], acc[nb][1], acc[nb][2], acc[nb][3],
                         a0, a1, a2, a3, bl[nb*2], bl[nb*2+1]);
                mma16816(acc[nb][0], acc[nb][1], acc[nb][2], acc[nb][3],
                         al[0], al[1], al[2], al[3], bh[nb*2], bh[nb*2+1]);
            }
        }

        // ---- spill fragments to gbuf [gate row][batch] ----
        #pragma unroll
        for (int nb = 0; nb < 4; nb++) {
            int col = n0 + nb * 8 + 2 * t4;
            *(float2*)&gb[(m0 + g8    ) * GBP + col] = make_float2(acc[nb][0], acc[nb][1]);
            *(float2*)&gb[(m0 + g8 + 8) * GBP + col] = make_float2(acc[nb][2], acc[nb][3]);
        }
        __syncthreads();

        // ---- gates + cell update (4 cells/thread) ----
        {
            const float* pf = (const float*)&gx0;
            const float* pi = (const float*)&gx1;
            const float* pc = (const float*)&gx2;
            const float* po = (const float*)&gx3;
            float hv[4];
            #pragma unroll
            for (int q = 0; q < 4; q++) {
                int l = lgrp + q;
                float gf = gb[(0*16 + l) * GBP + ub] + pf[q];
                float gi = gb[(1*16 + l) * GBP + ub] + pi[q];
                float gu = gb[(2*16 + l) * GBP + ub] + pc[q];
                float go = gb[(3*16 + l) * GBP + ub] + po[q];
                float f = fsigmoid(gf), ii = fsigmoid(gi);
                float u = ftanh(gu),    o = fsigmoid(go);
                c_reg[q] = f * c_reg[q] + ii * u;
                hv[q] = o * ftanh(c_reg[q]);
            }
            unsigned hiw[2], low[2];
            #pragma unroll
            for (int q = 0; q < 2; q++) {
                __nv_bfloat16 h0 = __float2bfloat16(hv[q*2]);
                __nv_bfloat16 h1 = __float2bfloat16(hv[q*2+1]);
                __nv_bfloat16 l0 = __float2bfloat16(hv[q*2]   - __bfloat162float(h0));
                __nv_bfloat16 l1 = __float2bfloat16(hv[q*2+1] - __bfloat162float(h1));
                hiw[q] = (unsigned)__bfloat16_as_ushort(h0) | ((unsigned)__bfloat16_as_ushort(h1) << 16);
                low[q] = (unsigned)__bfloat16_as_ushort(l0) | ((unsigned)__bfloat16_as_ushort(l1) << 16);
            }
            const int j0 = cta * 16 + lgrp;
            *(uint2*)&g_h[1 - par][0][ub * HH + j0] = make_uint2(hiw[0], hiw[1]);
            *(uint2*)&g_h[1 - par][1][ub * HH + j0] = make_uint2(low[0], low[1]);
            if (s == SS - 1) {
                #pragma unroll
                for (int q = 0; q < 4; q++) g_hfin[ub * HH + j0 + q] = hv[q];
            }
        }

        // ---- chip barrier (R3 mechanics, 32 CTAs) ----
        __threadfence();
        __syncthreads();
        if (t == 0) {
            unsigned arrived = atomicAdd(&g_bar_cnt, 1u) + 1u;
            if (arrived == (unsigned)NCTA * (unsigned)(s + 1)) {
                __threadfence();
                atomicAdd(&g_bar_gen, 1u);
            } else {
                unsigned gen;
                do {
                    asm volatile("ld.acquire.gpu.u32 %0, [%1];"
                                 : "=r"(gen) : "l"(&g_bar_gen) : "memory");
                } while (gen <= (unsigned)s);
            }
            __threadfence();
        }
        __syncthreads();
    }
}

// ---------------- output head ----------------
__global__ void __launch_bounds__(256) out_kernel(
    const float* __restrict__ Wout, const float* __restrict__ bout,
    float* __restrict__ out)
{
    __shared__ float hsh[HH];
    const int b = blockIdx.x, j = threadIdx.x;
    for (int k = j; k < HH; k += 256) hsh[k] = g_hfin[b * HH + k];
    __syncthreads();
    float a0 = 0.f, a1 = 0.f, a2 = 0.f, a3 = 0.f;
    #pragma unroll 4
    for (int k = 0; k < HH; k += 4) {
        a0 += hsh[k+0] * Wout[(size_t)(k+0)*OO + j];
        a1 += hsh[k+1] * Wout[(size_t)(k+1)*OO + j];
        a2 += hsh[k+2] * Wout[(size_t)(k+2)*OO + j];
        a3 += hsh[k+3] * Wout[(size_t)(k+3)*OO + j];
    }
    out[(size_t)b * OO + j] = a0 + a1 + a2 + a3 + bout[j];
}

// ---------------- launcher ----------------
extern "C" void kernel_launch(void* const* d_in, const int* in_sizes, int n_in,
                              void* d_out, int out_size)
{
    (void)in_sizes; (void)n_in; (void)out_size;
    const float* x    = (const float*)d_in[0];
    const float* Wf   = (const float*)d_in[1];
    const float* bf   = (const float*)d_in[2];
    const float* Wi   = (const float*)d_in[3];
    const float* bi   = (const float*)d_in[4];
    const float* Wc   = (const float*)d_in[5];
    const float* bc   = (const float*)d_in[6];
    const float* Wo   = (const float*)d_in[7];
    const float* bo   = (const float*)d_in[8];
    const float* Wout = (const float*)d_in[9];
    const float* bout = (const float*)d_in[10];
    float* out = (float*)d_out;

    cudaFuncSetAttribute(step_kernel,
                         cudaFuncAttributeMaxDynamicSharedMemorySize, SM_TOTAL);

    init_kernel<<<64, 256>>>();
    prepw_kernel<<<2048, 256>>>(Wf, Wi, Wc, Wo);
    precompute_kernel<<<dim3(G4/64, SS/64, BB), 256>>>(x, Wf, Wi, Wc, Wo, bf, bi, bc, bo);
    step_kernel<<<NCTA, 256, SM_TOTAL>>>();
    out_kernel<<<BB, 256>>>(Wout, bout, out);
}

// round 11
// speedup vs baseline: 1.1786x; 1.1786x over previous
#include <cuda_runtime.h>
#include <cuda_bf16.h>
#include <math.h>

#define BB 64
#define SS 1024
#define II 256
#define HH 512
#define OO 256
#define G4 2048
#define NCTA 64

// step smem map (bytes); pitch-1040 rows (bank-conflict-free ldmatrix, verified R10)
#define TPITCH 1040
#define SM_WHI 0
#define SM_WLO 33280
#define SM_HHI 66560
#define SM_HLO 133120
#define SM_TOTAL 199680
#define GBP 66            // k-partial buffer pitch (floats); aliases SM_HHI

// barrier tree: 8 groups of 8 CTAs (R6 mechanics, passed)
#define BAR_GRPS 8
#define BAR_GRP_SZ 8
#define BAR_PAD 32

__device__ __forceinline__ float fsigmoid(float x){ return __fdividef(1.0f, 1.0f + __expf(-x)); }
__device__ __forceinline__ float ftanh(float x){ return 1.0f - 2.0f*__fdividef(1.0f, __expf(2.0f*x)+1.0f); }
__device__ __forceinline__ unsigned long long pack2(float lo, float hi) {
    unsigned long long r; asm("mov.b64 %0, {%1, %2};" : "=l"(r) : "f"(lo), "f"(hi)); return r;
}
__device__ __forceinline__ unsigned long long ffma2(unsigned long long a, unsigned long long b, unsigned long long c) {
    unsigned long long d; asm("fma.rn.f32x2 %0, %1, %2, %3;" : "=l"(d) : "l"(a), "l"(b), "l"(c)); return d;
}
__device__ __forceinline__ float2 unpack2(unsigned long long v) {
    float2 f; asm("mov.b64 {%0, %1}, %2;" : "=f"(f.x), "=f"(f.y) : "l"(v)); return f;
}
__device__ __forceinline__ unsigned smem_u32(const void* p) {
    unsigned a;
    asm("{.reg .u64 t; cvta.to.shared.u64 t, %1; cvt.u32.u64 %0, t;}" : "=r"(a) : "l"(p));
    return a;
}
__device__ __forceinline__ void ldsm4(unsigned* r, unsigned addr) {
    asm volatile("ldmatrix.sync.aligned.m8n8.x4.shared.b16 {%0,%1,%2,%3}, [%4];"
                 : "=r"(r[0]), "=r"(r[1]), "=r"(r[2]), "=r"(r[3]) : "r"(addr));
}
__device__ __forceinline__ void mma16816(float* c, const unsigned* a, unsigned b0, unsigned b1) {
    asm volatile(
        "mma.sync.aligned.m16n8k16.row.col.f32.bf16.bf16.f32 "
        "{%0,%1,%2,%3},{%4,%5,%6,%7},{%8,%9},{%0,%1,%2,%3};"
        : "+f"(c[0]), "+f"(c[1]), "+f"(c[2]), "+f"(c[3])
        : "r"(a[0]), "r"(a[1]), "r"(a[2]), "r"(a[3]), "r"(b0), "r"(b1));
}

// ---------------- device scratch ----------------
__device__ float g_gx[(size_t)SS * BB * G4];                  // [s][b][col]
__device__ __align__(16) __nv_bfloat16 g_whi[NCTA][32 * 512]; // [cta][row][k]
__device__ __align__(16) __nv_bfloat16 g_wlo[NCTA][32 * 512];
__device__ __align__(16) __nv_bfloat16 g_h[2][2][BB * HH];    // [par][hi/lo][b][k]
__device__ float g_hfin[BB * HH];
__device__ unsigned g_grp_cnt[BAR_GRPS * BAR_PAD];
__device__ unsigned g_root_cnt, g_bar_gen;

// ---------------- init ----------------
__global__ void __launch_bounds__(256) init_kernel() {
    int t = blockIdx.x * 256 + threadIdx.x;
    if (t < 32768) ((uint4*)g_h)[t] = make_uint4(0,0,0,0);
    if (t < BAR_GRPS * BAR_PAD) g_grp_cnt[t] = 0u;
    if (t == 0) { g_root_cnt = 0u; g_bar_gen = 0u; }
}

// ---------------- W prep: bf16 hi/lo split, [cta][32 rows][512 k] ----------
__global__ void __launch_bounds__(256) prepw_kernel(
    const float* __restrict__ Wf, const float* __restrict__ Wi,
    const float* __restrict__ Wc, const float* __restrict__ Wo)
{
    int gid = blockIdx.x * 256 + threadIdx.x;    // 2048*256 = 524288
    int cta = gid >> 13;
    int rem = gid & 8191;
    int r   = rem >> 8;           // 0..31: gate row = g*8 + l
    int kp  = rem & 255;
    int k0  = kp * 2;
    int g = r >> 3, l = r & 7, j = cta * 8 + l;
    const float* W = (g==0)?Wf:(g==1)?Wi:(g==2)?Wc:Wo;
    #pragma unroll
    for (int q = 0; q < 2; q++) {
        int k = k0 + q;
        float w = W[(size_t)(II + k) * HH + j];
        __nv_bfloat16 hi = __float2bfloat16(w);
        __nv_bfloat16 lo = __float2bfloat16(w - __bfloat162float(hi));
        g_whi[cta][r * 512 + k] = hi;
        g_wlo[cta][r * 512 + k] = lo;
    }
}

// ---------------- input projection (unchanged, passing) ----------------
__global__ void __launch_bounds__(256) precompute_kernel(
    const float* __restrict__ x,
    const float* __restrict__ Wf, const float* __restrict__ Wi,
    const float* __restrict__ Wc, const float* __restrict__ Wo,
    const float* __restrict__ bf, const float* __restrict__ bi,
    const float* __restrict__ bc, const float* __restrict__ bo)
{
    __shared__ float As[16][64], Bs[16][64];
    const int b = blockIdx.z, s0 = blockIdx.y * 64, c0 = blockIdx.x * 64;
    const int g = c0 >> 9, j0 = c0 & 511;
    const float* W    = (g==0)?Wf:(g==1)?Wi:(g==2)?Wc:Wo;
    const float* bias = (g==0)?bf:(g==1)?bi:(g==2)?bc:bo;
    const int t = threadIdx.x, tx = t & 15, ty = t >> 4;
    unsigned long long acc[4][2] = {};
    const int sr = t >> 2, kq = (t & 3) * 4;
    for (int k0 = 0; k0 < II; k0 += 16) {
        float4 av = *(const float4*)&x[((size_t)b * SS + s0 + sr) * II + k0 + kq];
        As[kq+0][sr]=av.x; As[kq+1][sr]=av.y; As[kq+2][sr]=av.z; As[kq+3][sr]=av.w;
        #pragma unroll
        for (int i = 0; i < 4; i++) {
            int e = t + i * 256, kk = e >> 6, nn = e & 63;
            Bs[kk][nn] = W[(size_t)(k0 + kk) * HH + j0 + nn];
        }
        __syncthreads();
        #pragma unroll
        for (int k = 0; k < 16; k++) {
            float4 a = *(const float4*)&As[k][ty * 4];
            ulonglong2 w = *(const ulonglong2*)&Bs[k][tx * 4];
            unsigned long long aa;
            aa = pack2(a.x, a.x); acc[0][0]=ffma2(aa,w.x,acc[0][0]); acc[0][1]=ffma2(aa,w.y,acc[0][1]);
            aa = pack2(a.y, a.y); acc[1][0]=ffma2(aa,w.x,acc[1][0]); acc[1][1]=ffma2(aa,w.y,acc[1][1]);
            aa = pack2(a.z, a.z); acc[2][0]=ffma2(aa,w.x,acc[2][0]); acc[2][1]=ffma2(aa,w.y,acc[2][1]);
            aa = pack2(a.w, a.w); acc[3][0]=ffma2(aa,w.x,acc[3][0]); acc[3][1]=ffma2(aa,w.y,acc[3][1]);
        }
        __syncthreads();
    }
    float4 bv = *(const float4*)&bias[j0 + tx * 4];
    #pragma unroll
    for (int mi = 0; mi < 4; mi++) {
        int s = s0 + ty * 4 + mi;
        float2 q0 = unpack2(acc[mi][0]), q1 = unpack2(acc[mi][1]);
        float4 v; v.x=q0.x+bv.x; v.y=q0.y+bv.y; v.z=q1.x+bv.z; v.w=q1.y+bv.w;
        *(float4*)&g_gx[((size_t)s * BB + b) * G4 + c0 + tx * 4] = v;
    }
}

// ---------------- persistent mma.sync step kernel (v2 geometry) ----------
// CTA: M=32 gate rows (g*8+l), h cols cta*8..+7. 8 warps = 2 n-groups x 4 k-groups,
// warp tile m32 x n32 x k128. 3-pass bf16 split. gbuf aliases h-hi tile.
__global__ void __launch_bounds__(256, 1) step_kernel() {
    extern __shared__ __align__(16) unsigned char sm[];
    const int cta = blockIdx.x, t = threadIdx.x;
    const int wid = t >> 5, lane = t & 31;
    const int g8 = lane >> 2, t4 = lane & 3;
    const int ng = wid & 1, kg = wid >> 1;
    const int n0 = ng * 32;

    // --- W tiles -> smem once (2048 uint4 each) ---
    {
        const uint4* shi = (const uint4*)g_whi[cta];
        const uint4* slo = (const uint4*)g_wlo[cta];
        #pragma unroll
        for (int i = 0; i < 8; i++) {
            int ch = i * 256 + t;
            int r = ch >> 6, cc = ch & 63;
            *(uint4*)(sm + SM_WHI + r * TPITCH + cc * 16) = shi[ch];
            *(uint4*)(sm + SM_WLO + r * TPITCH + cc * 16) = slo[ch];
        }
    }
    __syncthreads();

    // ldmatrix lane bases (R10-verified conventions)
    const unsigned a_lr = (unsigned)((lane & 15) * TPITCH + ((lane & 16) ? 16 : 0));
    const unsigned ahi0 = smem_u32(sm + SM_WHI) + a_lr + (unsigned)(kg * 256);
    const unsigned ahi1 = ahi0 + 16u * TPITCH;
    const unsigned alo0 = ahi0 + (SM_WLO - SM_WHI);
    const unsigned alo1 = alo0 + 16u * TPITCH;
    const int brow = ((lane & 16) >> 1) + (lane & 7);
    const unsigned b_lr = (unsigned)(brow * TPITCH + ((lane & 8) ? 16 : 0));
    const unsigned bhi0 = smem_u32(sm + SM_HHI) + (unsigned)(n0 * TPITCH) + b_lr + (unsigned)(kg * 256);
    const unsigned bhi1 = bhi0 + 16u * TPITCH;
    const unsigned blo0 = bhi0 + (SM_HLO - SM_HHI);
    const unsigned blo1 = blo0 + 16u * TPITCH;

    const int ub = t >> 2, lp = (t & 3) * 2;   // update cell: batch, h-col pair
    float c_reg[2] = {};
    float* gb = (float*)(sm + SM_HHI);          // k-partials, aliases h-hi

    for (int s = 0; s < SS; s++) {
        const int par = s & 1;

        // ---- per-warp stage: own n32 x k128 quadrant of h hi+lo ----
        {
            const uint4* hs0 = (const uint4*)g_h[par][0];
            const uint4* hs1 = (const uint4*)g_h[par][1];
            #pragma unroll
            for (int i = 0; i < 16; i++) {
                int e = i * 32 + lane;
                int rr = e >> 4, cc = e & 15;
                int src = (n0 + rr) * 64 + kg * 16 + cc;
                unsigned dst = (unsigned)((n0 + rr) * TPITCH + kg * 256 + cc * 16);
                *(uint4*)(sm + SM_HHI + dst) = __ldcg(hs0 + src);
                *(uint4*)(sm + SM_HLO + dst) = __ldcg(hs1 + src);
            }
        }
        // Gx prefetch (independent of h)
        float2 gx[4];
        {
            const float* p = &g_gx[((size_t)s * BB + ub) * G4 + cta * 8 + lp];
            #pragma unroll
            for (int g = 0; g < 4; g++) gx[g] = *(const float2*)&p[g * 512];
        }
        __syncwarp();

        // ---- GEMM: 8 k-steps x (8 LDSM.x4 + 24 MMA) ----
        float acc[2][4][4] = {};
        #pragma unroll
        for (int kk = 0; kk < 8; kk++) {
            const unsigned ko = (unsigned)(kk * 32);
            unsigned ah0[4], ah1[4], al0[4], al1[4], bh0[4], bh1[4], bl0[4], bl1[4];
            ldsm4(ah0, ahi0 + ko); ldsm4(ah1, ahi1 + ko);
            ldsm4(al0, alo0 + ko); ldsm4(al1, alo1 + ko);
            ldsm4(bh0, bhi0 + ko); ldsm4(bh1, bhi1 + ko);
            ldsm4(bl0, blo0 + ko); ldsm4(bl1, blo1 + ko);
            #pragma unroll
            for (int mi = 0; mi < 2; mi++) {
                const unsigned* ah = mi ? ah1 : ah0;
                const unsigned* al = mi ? al1 : al0;
                #pragma unroll
                for (int nb = 0; nb < 4; nb++) {
                    const unsigned* bh = (nb < 2) ? bh0 : bh1;
                    const unsigned* bl = (nb < 2) ? bl0 : bl1;
                    const int ix = (nb & 1) * 2;
                    mma16816(acc[mi][nb], ah, bh[ix], bh[ix + 1]);
                    mma16816(acc[mi][nb], ah, bl[ix], bl[ix + 1]);
                    mma16816(acc[mi][nb], al, bh[ix], bh[ix + 1]);
                }
            }
        }
        __syncthreads();   // all LDSM done -> gbuf may overwrite h-hi

        // ---- spill k-partials: gbuf[kg*32 + row][batch] ----
        #pragma unroll
        for (int mi = 0; mi < 2; mi++) {
            #pragma unroll
            for (int nb = 0; nb < 4; nb++) {
                int row = kg * 32 + mi * 16 + g8;
                int col = n0 + nb * 8 + 2 * t4;
                *(float2*)&gb[row * GBP + col]       = make_float2(acc[mi][nb][0], acc[mi][nb][1]);
                *(float2*)&gb[(row + 8) * GBP + col] = make_float2(acc[mi][nb][2], acc[mi][nb][3]);
            }
        }
        __syncthreads();

        // ---- gates + cell update (2 cells/thread) ----
        {
            float hv[2];
            #pragma unroll
            for (int q = 0; q < 2; q++) {
                int l = lp + q;
                float gsum[4];
                #pragma unroll
                for (int g = 0; g < 4; g++) {
                    float v = 0.f;
                    #pragma unroll
                    for (int k = 0; k < 4; k++)
                        v += gb[(k * 32 + g * 8 + l) * GBP + ub];
                    gsum[g] = v;
                }
                float gf = gsum[0] + ((q == 0) ? gx[0].x : gx[0].y);
                float gi = gsum[1] + ((q == 0) ? gx[1].x : gx[1].y);
                float gu = gsum[2] + ((q == 0) ? gx[2].x : gx[2].y);
                float go = gsum[3] + ((q == 0) ? gx[3].x : gx[3].y);
                float f = fsigmoid(gf), ii = fsigmoid(gi);
                float u = ftanh(gu),    o = fsigmoid(go);
                c_reg[q] = f * c_reg[q] + ii * u;
                hv[q] = o * ftanh(c_reg[q]);
            }
            __nv_bfloat16 h0 = __float2bfloat16(hv[0]);
            __nv_bfloat16 h1 = __float2bfloat16(hv[1]);
            __nv_bfloat16 l0 = __float2bfloat16(hv[0] - __bfloat162float(h0));
            __nv_bfloat16 l1 = __float2bfloat16(hv[1] - __bfloat162float(h1));
            unsigned hiw = (unsigned)__bfloat16_as_ushort(h0) | ((unsigned)__bfloat16_as_ushort(h1) << 16);
            unsigned low = (unsigned)__bfloat16_as_ushort(l0) | ((unsigned)__bfloat16_as_ushort(l1) << 16);
            const int j0 = cta * 8 + lp;
            *(unsigned*)&g_h[1 - par][0][ub * HH + j0] = hiw;
            *(unsigned*)&g_h[1 - par][1][ub * HH + j0] = low;
            if (s == SS - 1) {
                g_hfin[ub * HH + j0]     = hv[0];
                g_hfin[ub * HH + j0 + 1] = hv[1];
            }
        }

        // ---- chip barrier: 2-level tree (R6 mechanics, 8x8) ----
        __threadfence();
        __syncthreads();
        if (t == 0) {
            const int grp = cta >> 3;
            unsigned a = atomicAdd(&g_grp_cnt[grp * BAR_PAD], 1u) + 1u;
            if (a == (unsigned)BAR_GRP_SZ * (unsigned)(s + 1)) {
                unsigned r = atomicAdd(&g_root_cnt, 1u) + 1u;
                if (r == (unsigned)BAR_GRPS * (unsigned)(s + 1)) {
                    __threadfence();
                    atomicAdd(&g_bar_gen, 1u);
                } else {
                    unsigned gen;
                    do {
                        asm volatile("ld.acquire.gpu.u32 %0, [%1];"
                                     : "=r"(gen) : "l"(&g_bar_gen) : "memory");
                    } while (gen <= (unsigned)s);
                }
            } else {
                unsigned gen;
                do {
                    asm volatile("ld.acquire.gpu.u32 %0, [%1];"
                                 : "=r"(gen) : "l"(&g_bar_gen) : "memory");
                } while (gen <= (unsigned)s);
            }
            __threadfence();
        }
        __syncthreads();
    }
}

// ---------------- output head ----------------
__global__ void __launch_bounds__(256) out_kernel(
    const float* __restrict__ Wout, const float* __restrict__ bout,
    float* __restrict__ out)
{
    __shared__ float hsh[HH];
    const int b = blockIdx.x, j = threadIdx.x;
    for (int k = j; k < HH; k += 256) hsh[k] = g_hfin[b * HH + k];
    __syncthreads();
    float a0 = 0.f, a1 = 0.f, a2 = 0.f, a3 = 0.f;
    #pragma unroll 4
    for (int k = 0; k < HH; k += 4) {
        a0 += hsh[k+0] * Wout[(size_t)(k+0)*OO + j];
        a1 += hsh[k+1] * Wout[(size_t)(k+1)*OO + j];
        a2 += hsh[k+2] * Wout[(size_t)(k+2)*OO + j];
        a3 += hsh[k+3] * Wout[(size_t)(k+3)*OO + j];
    }
    out[(size_t)b * OO + j] = a0 + a1 + a2 + a3 + bout[j];
}

// ---------------- launcher ----------------
extern "C" void kernel_launch(void* const* d_in, const int* in_sizes, int n_in,
                              void* d_out, int out_size)
{
    (void)in_sizes; (void)n_in; (void)out_size;
    const float* x    = (const float*)d_in[0];
    const float* Wf   = (const float*)d_in[1];
    const float* bf   = (const float*)d_in[2];
    const float* Wi   = (const float*)d_in[3];
    const float* bi   = (const float*)d_in[4];
    const float* Wc   = (const float*)d_in[5];
    const float* bc   = (const float*)d_in[6];
    const float* Wo   = (const float*)d_in[7];
    const float* bo   = (const float*)d_in[8];
    const float* Wout = (const float*)d_in[9];
    const float* bout = (const float*)d_in[10];
    float* out = (float*)d_out;

    cudaFuncSetAttribute(step_kernel,
                         cudaFuncAttributeMaxDynamicSharedMemorySize, SM_TOTAL);

    init_kernel<<<128, 256>>>();
    prepw_kernel<<<2048, 256>>>(Wf, Wi, Wc, Wo);
    precompute_kernel<<<dim3(G4/64, SS/64, BB), 256>>>(x, Wf, Wi, Wc, Wo, bf, bi, bc, bo);
    step_kernel<<<NCTA, 256, SM_TOTAL>>>();
    out_kernel<<<BB, 256>>>(Wout, bout, out);
}

// round 12
// speedup vs baseline: 1.2857x; 1.0909x over previous
#include <cuda_runtime.h>
#include <cuda_bf16.h>
#include <math.h>

#define BB 64
#define SS 1024
#define II 256
#define HH 512
#define OO 256
#define G4 2048
#define NCTA 64

// step smem map (bytes); pitch-1040 rows (verified R10/R11)
#define TPITCH 1040
#define SM_WHI 0
#define SM_WLO 33280
#define SM_HHI 66560
#define SM_HLO 133120
#define SM_TOTAL 199680
#define GBP 66

// precompute2 smem map: A/B tiles 64 rows x 256 bf16, pitch 528
#define XPITCH 528
#define PC_A_HI 0
#define PC_A_LO 33792
#define PC_B_HI 67584
#define PC_B_LO 101376
#define PC_TOTAL 135168
#define RP 66          // reduce-slab pitch (floats); slabs alias PC_A region
#define RSLAB 4224     // 64*66 floats per slab

// barrier tree: 8 groups of 8 CTAs (R6/R11 mechanics, passed)
#define BAR_GRPS 8
#define BAR_GRP_SZ 8
#define BAR_PAD 32

__device__ __forceinline__ float fsigmoid(float x){ return __fdividef(1.0f, 1.0f + __expf(-x)); }
__device__ __forceinline__ float ftanh(float x){ return 1.0f - 2.0f*__fdividef(1.0f, __expf(2.0f*x)+1.0f); }
__device__ __forceinline__ unsigned smem_u32(const void* p) {
    unsigned a;
    asm("{.reg .u64 t; cvta.to.shared.u64 t, %1; cvt.u32.u64 %0, t;}" : "=r"(a) : "l"(p));
    return a;
}
__device__ __forceinline__ void ldsm4(unsigned* r, unsigned addr) {
    asm volatile("ldmatrix.sync.aligned.m8n8.x4.shared.b16 {%0,%1,%2,%3}, [%4];"
                 : "=r"(r[0]), "=r"(r[1]), "=r"(r[2]), "=r"(r[3]) : "r"(addr));
}
__device__ __forceinline__ void mma16816(float* c, const unsigned* a, unsigned b0, unsigned b1) {
    asm volatile(
        "mma.sync.aligned.m16n8k16.row.col.f32.bf16.bf16.f32 "
        "{%0,%1,%2,%3},{%4,%5,%6,%7},{%8,%9},{%0,%1,%2,%3};"
        : "+f"(c[0]), "+f"(c[1]), "+f"(c[2]), "+f"(c[3])
        : "r"(a[0]), "r"(a[1]), "r"(a[2]), "r"(a[3]), "r"(b0), "r"(b1));
}
__device__ __forceinline__ unsigned bf2pack(float a, float b) {
    __nv_bfloat16 x = __float2bfloat16(a), y = __float2bfloat16(b);
    return (unsigned)__bfloat16_as_ushort(x) | ((unsigned)__bfloat16_as_ushort(y) << 16);
}

// ---------------- device scratch ----------------
__device__ float g_gx[(size_t)SS * BB * G4];                   // [s][b][col]
__device__ __align__(16) __nv_bfloat16 g_whi[NCTA][32 * 512];  // recurrent W
__device__ __align__(16) __nv_bfloat16 g_wlo[NCTA][32 * 512];
__device__ __align__(16) __nv_bfloat16 g_xhi[(size_t)BB * SS * II];  // x split
__device__ __align__(16) __nv_bfloat16 g_xlo[(size_t)BB * SS * II];
__device__ __align__(16) __nv_bfloat16 g_wxthi[G4 * II];       // Wx^T [col][k]
__device__ __align__(16) __nv_bfloat16 g_wxtlo[G4 * II];
__device__ __align__(16) __nv_bfloat16 g_h[2][2][BB * HH];     // [par][hi/lo][b][k]
__device__ float g_hfin[BB * HH];
__device__ unsigned g_grp_cnt[BAR_GRPS * BAR_PAD];
__device__ unsigned g_root_cnt, g_bar_gen;

// ---------------- init ----------------
__global__ void __launch_bounds__(256) init_kernel() {
    int t = blockIdx.x * 256 + threadIdx.x;
    if (t < 32768) ((uint4*)g_h)[t] = make_uint4(0,0,0,0);
    if (t < BAR_GRPS * BAR_PAD) g_grp_cnt[t] = 0u;
    if (t == 0) { g_root_cnt = 0u; g_bar_gen = 0u; }
}

// ---------------- recurrent W prep (R11, passed) ----------------
__global__ void __launch_bounds__(256) prepw_kernel(
    const float* __restrict__ Wf, const float* __restrict__ Wi,
    const float* __restrict__ Wc, const float* __restrict__ Wo)
{
    int gid = blockIdx.x * 256 + threadIdx.x;
    int cta = gid >> 13;
    int rem = gid & 8191;
    int r   = rem >> 8;
    int kp  = rem & 255;
    int k0  = kp * 2;
    int g = r >> 3, l = r & 7, j = cta * 8 + l;
    const float* W = (g==0)?Wf:(g==1)?Wi:(g==2)?Wc:Wo;
    #pragma unroll
    for (int q = 0; q < 2; q++) {
        int k = k0 + q;
        float w = W[(size_t)(II + k) * HH + j];
        __nv_bfloat16 hi = __float2bfloat16(w);
        __nv_bfloat16 lo = __float2bfloat16(w - __bfloat162float(hi));
        g_whi[cta][r * 512 + k] = hi;
        g_wlo[cta][r * 512 + k] = lo;
    }
}

// ---------------- x split: fp32 -> bf16 hi/lo (same layout) ----------------
__global__ void __launch_bounds__(256) prepx_kernel(const float* __restrict__ x) {
    size_t gid = (size_t)blockIdx.x * 256 + threadIdx.x;   // 4,194,304 threads
    float4 v = *(const float4*)&x[gid * 4];
    __nv_bfloat16 h0 = __float2bfloat16(v.x), h1 = __float2bfloat16(v.y);
    __nv_bfloat16 h2 = __float2bfloat16(v.z), h3 = __float2bfloat16(v.w);
    uint2 hw, lw;
    hw.x = (unsigned)__bfloat16_as_ushort(h0) | ((unsigned)__bfloat16_as_ushort(h1) << 16);
    hw.y = (unsigned)__bfloat16_as_ushort(h2) | ((unsigned)__bfloat16_as_ushort(h3) << 16);
    lw.x = bf2pack(v.x - __bfloat162float(h0), v.y - __bfloat162float(h1));
    lw.y = bf2pack(v.z - __bfloat162float(h2), v.w - __bfloat162float(h3));
    ((uint2*)g_xhi)[gid] = hw;
    ((uint2*)g_xlo)[gid] = lw;
}

// ---------------- Wx transpose+split: [col][k] hi/lo ----------------
__global__ void __launch_bounds__(256) prepwx_kernel(
    const float* __restrict__ Wf, const float* __restrict__ Wi,
    const float* __restrict__ Wc, const float* __restrict__ Wo)
{
    int gid = blockIdx.x * 256 + threadIdx.x;    // 2048*128 = 262144
    int col = gid >> 7;
    int kp  = gid & 127;
    int g = col >> 9, j = col & 511;
    const float* W = (g==0)?Wf:(g==1)?Wi:(g==2)?Wc:Wo;
    #pragma unroll
    for (int q = 0; q < 2; q++) {
        int k = kp * 2 + q;
        float w = W[(size_t)k * HH + j];           // x-part rows 0..255
        __nv_bfloat16 hi = __float2bfloat16(w);
        g_wxthi[col * II + k] = hi;
        g_wxtlo[col * II + k] = __float2bfloat16(w - __bfloat162float(hi));
    }
}

// ---------------- precompute v2: Gx = x @ Wx + b via mma.sync -------------
// CTA tile M=64(s) x N=64(col), K=256. 8 warps = 2m x 2n x 2k (warp m32n32k128).
__global__ void __launch_bounds__(256) precompute2_kernel(
    const float* __restrict__ bf, const float* __restrict__ bi,
    const float* __restrict__ bc, const float* __restrict__ bo)
{
    extern __shared__ __align__(16) unsigned char sm[];
    const int ct = blockIdx.x;          // col tile 0..31
    const int st = blockIdx.y;          // s tile 0..15
    const int b  = blockIdx.z;
    const int t = threadIdx.x, lane = t & 31, wid = t >> 5;
    const int g8 = lane >> 2, t4 = lane & 3;
    const int mg = wid & 1, ngp = (wid >> 1) & 1, kg = wid >> 2;

    // stage A (x tile, 64 s-rows x 256 k, contiguous) and B (Wx^T tile)
    {
        const uint4* xh = (const uint4*)&g_xhi[((size_t)b * SS + st * 64) * II];
        const uint4* xl = (const uint4*)&g_xlo[((size_t)b * SS + st * 64) * II];
        const uint4* wh = (const uint4*)&g_wxthi[(ct * 64) * II];
        const uint4* wl = (const uint4*)&g_wxtlo[(ct * 64) * II];
        #pragma unroll
        for (int i = 0; i < 8; i++) {
            int ch = i * 256 + t;                 // 2048 chunks of 16B
            int r = ch >> 5, cc = ch & 31;
            unsigned dst = (unsigned)(r * XPITCH + cc * 16);
            *(uint4*)(sm + PC_A_HI + dst) = __ldg(xh + ch);
            *(uint4*)(sm + PC_A_LO + dst) = __ldg(xl + ch);
            *(uint4*)(sm + PC_B_HI + dst) = __ldg(wh + ch);
            *(uint4*)(sm + PC_B_LO + dst) = __ldg(wl + ch);
        }
    }
    __syncthreads();

    // fragment bases (R11-verified conventions, pitch XPITCH)
    const unsigned a_lr = (unsigned)((lane & 15) * XPITCH + ((lane & 16) ? 16 : 0));
    const unsigned ahi0 = smem_u32(sm + PC_A_HI) + a_lr
                        + (unsigned)(mg * 32 * XPITCH + kg * 256);
    const unsigned ahi1 = ahi0 + 16u * XPITCH;
    const unsigned alo0 = ahi0 + (PC_A_LO - PC_A_HI);
    const unsigned alo1 = alo0 + 16u * XPITCH;
    const int brow = ((lane & 16) >> 1) + (lane & 7);
    const unsigned b_lr = (unsigned)(brow * XPITCH + ((lane & 8) ? 16 : 0));
    const unsigned bhi0 = smem_u32(sm + PC_B_HI) + b_lr
                        + (unsigned)(ngp * 32 * XPITCH + kg * 256);
    const unsigned bhi1 = bhi0 + 16u * XPITCH;
    const unsigned blo0 = bhi0 + (PC_B_LO - PC_B_HI);
    const unsigned blo1 = blo0 + 16u * XPITCH;

    // GEMM: 8 k-steps x (8 LDSM.x4 + 24 MMA)  [R11 inner loop]
    float acc[2][4][4] = {};
    #pragma unroll
    for (int kk = 0; kk < 8; kk++) {
        const unsigned ko = (unsigned)(kk * 32);
        unsigned ah0[4], ah1[4], al0[4], al1[4], bh0[4], bh1[4], bl0[4], bl1[4];
        ldsm4(ah0, ahi0 + ko); ldsm4(ah1, ahi1 + ko);
        ldsm4(al0, alo0 + ko); ldsm4(al1, alo1 + ko);
        ldsm4(bh0, bhi0 + ko); ldsm4(bh1, bhi1 + ko);
        ldsm4(bl0, blo0 + ko); ldsm4(bl1, blo1 + ko);
        #pragma unroll
        for (int mi = 0; mi < 2; mi++) {
            const unsigned* ah = mi ? ah1 : ah0;
            const unsigned* al = mi ? al1 : al0;
            #pragma unroll
            for (int nb = 0; nb < 4; nb++) {
                const unsigned* bh = (nb < 2) ? bh0 : bh1;
                const unsigned* bl = (nb < 2) ? bl0 : bl1;
                const int ix = (nb & 1) * 2;
                mma16816(acc[mi][nb], ah, bh[ix], bh[ix + 1]);
                mma16816(acc[mi][nb], ah, bl[ix], bl[ix + 1]);
                mma16816(acc[mi][nb], al, bh[ix], bh[ix + 1]);
            }
        }
    }
    __syncthreads();   // LDSM done; reduce slabs alias the A region

    // spill k-partials: slab[kg][s row][col]
    float* rb = (float*)sm;
    #pragma unroll
    for (int mi = 0; mi < 2; mi++) {
        #pragma unroll
        for (int nb = 0; nb < 4; nb++) {
            int row = mg * 32 + mi * 16 + g8;
            int col = ngp * 32 + nb * 8 + 2 * t4;
            *(float2*)&rb[kg * RSLAB + row * RP + col]
                = make_float2(acc[mi][nb][0], acc[mi][nb][1]);
            *(float2*)&rb[kg * RSLAB + (row + 8) * RP + col]
                = make_float2(acc[mi][nb][2], acc[mi][nb][3]);
        }
    }
    __syncthreads();

    // epilogue: sum 2 slabs + bias, write g_gx[s][b][col]
    {
        const int g = ct >> 3;
        const float* bias = (g==0)?bf:(g==1)?bi:(g==2)?bc:bo;
        const int j0 = (ct & 7) * 64;
        const int r = t >> 2, cb = (t & 3) * 16;
        float* dst = &g_gx[((size_t)(st * 64 + r) * BB + b) * G4 + ct * 64 + cb];
        #pragma unroll
        for (int v4 = 0; v4 < 4; v4++) {
            float4 v;
            float* o = (float*)&v;
            #pragma unroll
            for (int q = 0; q < 4; q++) {
                int col = cb + v4 * 4 + q;
                o[q] = rb[r * RP + col] + rb[RSLAB + r * RP + col] + bias[j0 + col];
            }
            *(float4*)&dst[v4 * 4] = v;
        }
    }
}

// ---------------- persistent mma.sync step kernel (R11 verbatim) ----------
__global__ void __launch_bounds__(256, 1) step_kernel() {
    extern __shared__ __align__(16) unsigned char sm[];
    const int cta = blockIdx.x, t = threadIdx.x;
    const int wid = t >> 5, lane = t & 31;
    const int g8 = lane >> 2, t4 = lane & 3;
    const int ng = wid & 1, kg = wid >> 1;
    const int n0 = ng * 32;

    {
        const uint4* shi = (const uint4*)g_whi[cta];
        const uint4* slo = (const uint4*)g_wlo[cta];
        #pragma unroll
        for (int i = 0; i < 8; i++) {
            int ch = i * 256 + t;
            int r = ch >> 6, cc = ch & 63;
            *(uint4*)(sm + SM_WHI + r * TPITCH + cc * 16) = shi[ch];
            *(uint4*)(sm + SM_WLO + r * TPITCH + cc * 16) = slo[ch];
        }
    }
    __syncthreads();

    const unsigned a_lr = (unsigned)((lane & 15) * TPITCH + ((lane & 16) ? 16 : 0));
    const unsigned ahi0 = smem_u32(sm + SM_WHI) + a_lr + (unsigned)(kg * 256);
    const unsigned ahi1 = ahi0 + 16u * TPITCH;
    const unsigned alo0 = ahi0 + (SM_WLO - SM_WHI);
    const unsigned alo1 = alo0 + 16u * TPITCH;
    const int brow = ((lane & 16) >> 1) + (lane & 7);
    const unsigned b_lr = (unsigned)(brow * TPITCH + ((lane & 8) ? 16 : 0));
    const unsigned bhi0 = smem_u32(sm + SM_HHI) + (unsigned)(n0 * TPITCH) + b_lr + (unsigned)(kg * 256);
    const unsigned bhi1 = bhi0 + 16u * TPITCH;
    const unsigned blo0 = bhi0 + (SM_HLO - SM_HHI);
    const unsigned blo1 = blo0 + 16u * TPITCH;

    const int ub = t >> 2, lp = (t & 3) * 2;
    float c_reg[2] = {};
    float* gb = (float*)(sm + SM_HHI);

    for (int s = 0; s < SS; s++) {
        const int par = s & 1;

        {
            const uint4* hs0 = (const uint4*)g_h[par][0];
            const uint4* hs1 = (const uint4*)g_h[par][1];
            #pragma unroll
            for (int i = 0; i < 16; i++) {
                int e = i * 32 + lane;
                int rr = e >> 4, cc = e & 15;
                int src = (n0 + rr) * 64 + kg * 16 + cc;
                unsigned dst = (unsigned)((n0 + rr) * TPITCH + kg * 256 + cc * 16);
                *(uint4*)(sm + SM_HHI + dst) = __ldcg(hs0 + src);
                *(uint4*)(sm + SM_HLO + dst) = __ldcg(hs1 + src);
            }
        }
        float2 gx[4];
        {
            const float* p = &g_gx[((size_t)s * BB + ub) * G4 + cta * 8 + lp];
            #pragma unroll
            for (int g = 0; g < 4; g++) gx[g] = *(const float2*)&p[g * 512];
        }
        __syncwarp();

        float acc[2][4][4] = {};
        #pragma unroll
        for (int kk = 0; kk < 8; kk++) {
            const unsigned ko = (unsigned)(kk * 32);
            unsigned ah0[4], ah1[4], al0[4], al1[4], bh0[4], bh1[4], bl0[4], bl1[4];
            ldsm4(ah0, ahi0 + ko); ldsm4(ah1, ahi1 + ko);
            ldsm4(al0, alo0 + ko); ldsm4(al1, alo1 + ko);
            ldsm4(bh0, bhi0 + ko); ldsm4(bh1, bhi1 + ko);
            ldsm4(bl0, blo0 + ko); ldsm4(bl1, blo1 + ko);
            #pragma unroll
            for (int mi = 0; mi < 2; mi++) {
                const unsigned* ah = mi ? ah1 : ah0;
                const unsigned* al = mi ? al1 : al0;
                #pragma unroll
                for (int nb = 0; nb < 4; nb++) {
                    const unsigned* bh = (nb < 2) ? bh0 : bh1;
                    const unsigned* bl = (nb < 2) ? bl0 : bl1;
                    const int ix = (nb & 1) * 2;
                    mma16816(acc[mi][nb], ah, bh[ix], bh[ix + 1]);
                    mma16816(acc[mi][nb], ah, bl[ix], bl[ix + 1]);
                    mma16816(acc[mi][nb], al, bh[ix], bh[ix + 1]);
                }
            }
        }
        __syncthreads();

        #pragma unroll
        for (int mi = 0; mi < 2; mi++) {
            #pragma unroll
            for (int nb = 0; nb < 4; nb++) {
                int row = kg * 32 + mi * 16 + g8;
                int col = n0 + nb * 8 + 2 * t4;
                *(float2*)&gb[row * GBP + col]       = make_float2(acc[mi][nb][0], acc[mi][nb][1]);
                *(float2*)&gb[(row + 8) * GBP + col] = make_float2(acc[mi][nb][2], acc[mi][nb][3]);
            }
        }
        __syncthreads();

        {
            float hv[2];
            #pragma unroll
            for (int q = 0; q < 2; q++) {
                int l = lp + q;
                float gsum[4];
                #pragma unroll
                for (int g = 0; g < 4; g++) {
                    float v = 0.f;
                    #pragma unroll
                    for (int k = 0; k < 4; k++)
                        v += gb[(k * 32 + g * 8 + l) * GBP + ub];
                    gsum[g] = v;
                }
                float gf = gsum[0] + ((q == 0) ? gx[0].x : gx[0].y);
                float gi = gsum[1] + ((q == 0) ? gx[1].x : gx[1].y);
                float gu = gsum[2] + ((q == 0) ? gx[2].x : gx[2].y);
                float go = gsum[3] + ((q == 0) ? gx[3].x : gx[3].y);
                float f = fsigmoid(gf), ii = fsigmoid(gi);
                float u = ftanh(gu),    o = fsigmoid(go);
                c_reg[q] = f * c_reg[q] + ii * u;
                hv[q] = o * ftanh(c_reg[q]);
            }
            __nv_bfloat16 h0 = __float2bfloat16(hv[0]);
            __nv_bfloat16 h1 = __float2bfloat16(hv[1]);
            unsigned hiw = (unsigned)__bfloat16_as_ushort(h0) | ((unsigned)__bfloat16_as_ushort(h1) << 16);
            unsigned low = bf2pack(hv[0] - __bfloat162float(h0), hv[1] - __bfloat162float(h1));
            const int j0 = cta * 8 + lp;
            *(unsigned*)&g_h[1 - par][0][ub * HH + j0] = hiw;
            *(unsigned*)&g_h[1 - par][1][ub * HH + j0] = low;
            if (s == SS - 1) {
                g_hfin[ub * HH + j0]     = hv[0];
                g_hfin[ub * HH + j0 + 1] = hv[1];
            }
        }

        __threadfence();
        __syncthreads();
        if (t == 0) {
            const int grp = cta >> 3;
            unsigned a = atomicAdd(&g_grp_cnt[grp * BAR_PAD], 1u) + 1u;
            if (a == (unsigned)BAR_GRP_SZ * (unsigned)(s + 1)) {
                unsigned r = atomicAdd(&g_root_cnt, 1u) + 1u;
                if (r == (unsigned)BAR_GRPS * (unsigned)(s + 1)) {
                    __threadfence();
                    atomicAdd(&g_bar_gen, 1u);
                } else {
                    unsigned gen;
                    do {
                        asm volatile("ld.acquire.gpu.u32 %0, [%1];"
                                     : "=r"(gen) : "l"(&g_bar_gen) : "memory");
                    } while (gen <= (unsigned)s);
                }
            } else {
                unsigned gen;
                do {
                    asm volatile("ld.acquire.gpu.u32 %0, [%1];"
                                 : "=r"(gen) : "l"(&g_bar_gen) : "memory");
                } while (gen <= (unsigned)s);
            }
            __threadfence();
        }
        __syncthreads();
    }
}

// ---------------- output head ----------------
__global__ void __launch_bounds__(256) out_kernel(
    const float* __restrict__ Wout, const float* __restrict__ bout,
    float* __restrict__ out)
{
    __shared__ float hsh[HH];
    const int b = blockIdx.x, j = threadIdx.x;
    for (int k = j; k < HH; k += 256) hsh[k] = g_hfin[b * HH + k];
    __syncthreads();
    float a0 = 0.f, a1 = 0.f, a2 = 0.f, a3 = 0.f;
    #pragma unroll 4
    for (int k = 0; k < HH; k += 4) {
        a0 += hsh[k+0] * Wout[(size_t)(k+0)*OO + j];
        a1 += hsh[k+1] * Wout[(size_t)(k+1)*OO + j];
        a2 += hsh[k+2] * Wout[(size_t)(k+2)*OO + j];
        a3 += hsh[k+3] * Wout[(size_t)(k+3)*OO + j];
    }
    out[(size_t)b * OO + j] = a0 + a1 + a2 + a3 + bout[j];
}

// ---------------- launcher ----------------
extern "C" void kernel_launch(void* const* d_in, const int* in_sizes, int n_in,
                              void* d_out, int out_size)
{
    (void)in_sizes; (void)n_in; (void)out_size;
    const float* x    = (const float*)d_in[0];
    const float* Wf   = (const float*)d_in[1];
    const float* bf   = (const float*)d_in[2];
    const float* Wi   = (const float*)d_in[3];
    const float* bi   = (const float*)d_in[4];
    const float* Wc   = (const float*)d_in[5];
    const float* bc   = (const float*)d_in[6];
    const float* Wo   = (const float*)d_in[7];
    const float* bo   = (const float*)d_in[8];
    const float* Wout = (const float*)d_in[9];
    const float* bout = (const float*)d_in[10];
    float* out = (float*)d_out;

    cudaFuncSetAttribute(step_kernel,
                         cudaFuncAttributeMaxDynamicSharedMemorySize, SM_TOTAL);
    cudaFuncSetAttribute(precompute2_kernel,
                         cudaFuncAttributeMaxDynamicSharedMemorySize, PC_TOTAL);

    init_kernel<<<128, 256>>>();
    prepw_kernel<<<2048, 256>>>(Wf, Wi, Wc, Wo);
    prepx_kernel<<<16384, 256>>>(x);
    prepwx_kernel<<<1024, 256>>>(Wf, Wi, Wc, Wo);
    precompute2_kernel<<<dim3(32, 16, BB), 256, PC_TOTAL>>>(bf, bi, bc, bo);
    step_kernel<<<NCTA, 256, SM_TOTAL>>>();
    out_kernel<<<BB, 256>>>(Wout, bout, out);
}

// round 14
// speedup vs baseline: 1.4558x; 1.1322x over previous
#include <cuda_runtime.h>
#include <cuda_bf16.h>
#include <math.h>

#define BB 64
#define SS 1024
#define II 256
#define HH 512
#define OO 256
#define G4 2048
#define NCTA 64

// step smem map (bytes); pitch-1040 rows (verified R10/R11)
#define TPITCH 1040
#define SM_WHI 0
#define SM_WLO 33280
#define SM_HHI 66560
#define SM_HLO 133120
#define SM_TOTAL 199680
#define GBP 66

// precompute2 smem map: A/B tiles 64 rows x 256 bf16, pitch 528
#define XPITCH 528
#define PC_A_HI 0
#define PC_A_LO 33792
#define PC_B_HI 67584
#define PC_B_LO 101376
#define PC_TOTAL 135168
#define RP 66
#define RSLAB 4224

#define FLAG_PAD 32      // 128B stride between CTA flags

__device__ __forceinline__ float fsigmoid(float x){ return __fdividef(1.0f, 1.0f + __expf(-x)); }
__device__ __forceinline__ float ftanh(float x){ return 1.0f - 2.0f*__fdividef(1.0f, __expf(2.0f*x)+1.0f); }
__device__ __forceinline__ unsigned smem_u32(const void* p) {
    unsigned a;
    asm("{.reg .u64 t; cvta.to.shared.u64 t, %1; cvt.u32.u64 %0, t;}" : "=r"(a) : "l"(p));
    return a;
}
__device__ __forceinline__ void ldsm4(unsigned* r, unsigned addr) {
    asm volatile("ldmatrix.sync.aligned.m8n8.x4.shared.b16 {%0,%1,%2,%3}, [%4];"
                 : "=r"(r[0]), "=r"(r[1]), "=r"(r[2]), "=r"(r[3]) : "r"(addr));
}
__device__ __forceinline__ void mma16816(float* c, const unsigned* a, unsigned b0, unsigned b1) {
    asm volatile(
        "mma.sync.aligned.m16n8k16.row.col.f32.bf16.bf16.f32 "
        "{%0,%1,%2,%3},{%4,%5,%6,%7},{%8,%9},{%0,%1,%2,%3};"
        : "+f"(c[0]), "+f"(c[1]), "+f"(c[2]), "+f"(c[3])
        : "r"(a[0]), "r"(a[1]), "r"(a[2]), "r"(a[3]), "r"(b0), "r"(b1));
}
__device__ __forceinline__ unsigned bf2pack(float a, float b) {
    __nv_bfloat16 x = __float2bfloat16(a), y = __float2bfloat16(b);
    return (unsigned)__bfloat16_as_ushort(x) | ((unsigned)__bfloat16_as_ushort(y) << 16);
}

// ---------------- device scratch ----------------
__device__ float g_gx[(size_t)SS * BB * G4];
__device__ __align__(16) __nv_bfloat16 g_whi[NCTA][32 * 512];
__device__ __align__(16) __nv_bfloat16 g_wlo[NCTA][32 * 512];
__device__ __align__(16) __nv_bfloat16 g_xhi[(size_t)BB * SS * II];
__device__ __align__(16) __nv_bfloat16 g_xlo[(size_t)BB * SS * II];
__device__ __align__(16) __nv_bfloat16 g_wxthi[G4 * II];
__device__ __align__(16) __nv_bfloat16 g_wxtlo[G4 * II];
__device__ __align__(16) __nv_bfloat16 g_h[2][2][BB * HH];
__device__ float g_hfin[BB * HH];
__device__ unsigned g_flags[NCTA * FLAG_PAD];   // per-CTA step flags

// ---------------- init ----------------
__global__ void __launch_bounds__(256) init_kernel() {
    int t = blockIdx.x * 256 + threadIdx.x;
    if (t < 32768) ((uint4*)g_h)[t] = make_uint4(0,0,0,0);
    if (t < NCTA * FLAG_PAD) g_flags[t] = 0u;
}

// ---------------- recurrent W prep (R11/R12, passed) ----------------
__global__ void __launch_bounds__(256) prepw_kernel(
    const float* __restrict__ Wf, const float* __restrict__ Wi,
    const float* __restrict__ Wc, const float* __restrict__ Wo)
{
    int gid = blockIdx.x * 256 + threadIdx.x;
    int cta = gid >> 13;
    int rem = gid & 8191;
    int r   = rem >> 8;
    int kp  = rem & 255;
    int k0  = kp * 2;
    int g = r >> 3, l = r & 7, j = cta * 8 + l;
    const float* W = (g==0)?Wf:(g==1)?Wi:(g==2)?Wc:Wo;
    #pragma unroll
    for (int q = 0; q < 2; q++) {
        int k = k0 + q;
        float w = W[(size_t)(II + k) * HH + j];
        __nv_bfloat16 hi = __float2bfloat16(w);
        __nv_bfloat16 lo = __float2bfloat16(w - __bfloat162float(hi));
        g_whi[cta][r * 512 + k] = hi;
        g_wlo[cta][r * 512 + k] = lo;
    }
}

// ---------------- x split (R12, passed) ----------------
__global__ void __launch_bounds__(256) prepx_kernel(const float* __restrict__ x) {
    size_t gid = (size_t)blockIdx.x * 256 + threadIdx.x;
    float4 v = *(const float4*)&x[gid * 4];
    __nv_bfloat16 h0 = __float2bfloat16(v.x), h1 = __float2bfloat16(v.y);
    __nv_bfloat16 h2 = __float2bfloat16(v.z), h3 = __float2bfloat16(v.w);
    uint2 hw, lw;
    hw.x = (unsigned)__bfloat16_as_ushort(h0) | ((unsigned)__bfloat16_as_ushort(h1) << 16);
    hw.y = (unsigned)__bfloat16_as_ushort(h2) | ((unsigned)__bfloat16_as_ushort(h3) << 16);
    lw.x = bf2pack(v.x - __bfloat162float(h0), v.y - __bfloat162float(h1));
    lw.y = bf2pack(v.z - __bfloat162float(h2), v.w - __bfloat162float(h3));
    ((uint2*)g_xhi)[gid] = hw;
    ((uint2*)g_xlo)[gid] = lw;
}

// ---------------- Wx transpose+split (R12, passed) ----------------
__global__ void __launch_bounds__(256) prepwx_kernel(
    const float* __restrict__ Wf, const float* __restrict__ Wi,
    const float* __restrict__ Wc, const float* __restrict__ Wo)
{
    int gid = blockIdx.x * 256 + threadIdx.x;
    int col = gid >> 7;
    int kp  = gid & 127;
    int g = col >> 9, j = col & 511;
    const float* W = (g==0)?Wf:(g==1)?Wi:(g==2)?Wc:Wo;
    #pragma unroll
    for (int q = 0; q < 2; q++) {
        int k = kp * 2 + q;
        float w = W[(size_t)k * HH + j];
        __nv_bfloat16 hi = __float2bfloat16(w);
        g_wxthi[col * II + k] = hi;
        g_wxtlo[col * II + k] = __float2bfloat16(w - __bfloat162float(hi));
    }
}

// ---------------- precompute v2 (R12, passed, verbatim) -------------------
__global__ void __launch_bounds__(256) precompute2_kernel(
    const float* __restrict__ bf, const float* __restrict__ bi,
    const float* __restrict__ bc, const float* __restrict__ bo)
{
    extern __shared__ __align__(16) unsigned char sm[];
    const int ct = blockIdx.x;
    const int st = blockIdx.y;
    const int b  = blockIdx.z;
    const int t = threadIdx.x, lane = t & 31, wid = t >> 5;
    const int g8 = lane >> 2, t4 = lane & 3;
    const int mg = wid & 1, ngp = (wid >> 1) & 1, kg = wid >> 2;

    {
        const uint4* xh = (const uint4*)&g_xhi[((size_t)b * SS + st * 64) * II];
        const uint4* xl = (const uint4*)&g_xlo[((size_t)b * SS + st * 64) * II];
        const uint4* wh = (const uint4*)&g_wxthi[(ct * 64) * II];
        const uint4* wl = (const uint4*)&g_wxtlo[(ct * 64) * II];
        #pragma unroll
        for (int i = 0; i < 8; i++) {
            int ch = i * 256 + t;
            int r = ch >> 5, cc = ch & 31;
            unsigned dst = (unsigned)(r * XPITCH + cc * 16);
            *(uint4*)(sm + PC_A_HI + dst) = __ldg(xh + ch);
            *(uint4*)(sm + PC_A_LO + dst) = __ldg(xl + ch);
            *(uint4*)(sm + PC_B_HI + dst) = __ldg(wh + ch);
            *(uint4*)(sm + PC_B_LO + dst) = __ldg(wl + ch);
        }
    }
    __syncthreads();

    const unsigned a_lr = (unsigned)((lane & 15) * XPITCH + ((lane & 16) ? 16 : 0));
    const unsigned ahi0 = smem_u32(sm + PC_A_HI) + a_lr
                        + (unsigned)(mg * 32 * XPITCH + kg * 256);
    const unsigned ahi1 = ahi0 + 16u * XPITCH;
    const unsigned alo0 = ahi0 + (PC_A_LO - PC_A_HI);
    const unsigned alo1 = alo0 + 16u * XPITCH;
    const int brow = ((lane & 16) >> 1) + (lane & 7);
    const unsigned b_lr = (unsigned)(brow * XPITCH + ((lane & 8) ? 16 : 0));
    const unsigned bhi0 = smem_u32(sm + PC_B_HI) + b_lr
                        + (unsigned)(ngp * 32 * XPITCH + kg * 256);
    const unsigned bhi1 = bhi0 + 16u * XPITCH;
    const unsigned blo0 = bhi0 + (PC_B_LO - PC_B_HI);
    const unsigned blo1 = blo0 + 16u * XPITCH;

    float acc[2][4][4] = {};
    #pragma unroll
    for (int kk = 0; kk < 8; kk++) {
        const unsigned ko = (unsigned)(kk * 32);
        unsigned ah0[4], ah1[4], al0[4], al1[4], bh0[4], bh1[4], bl0[4], bl1[4];
        ldsm4(ah0, ahi0 + ko); ldsm4(ah1, ahi1 + ko);
        ldsm4(al0, alo0 + ko); ldsm4(al1, alo1 + ko);
        ldsm4(bh0, bhi0 + ko); ldsm4(bh1, bhi1 + ko);
        ldsm4(bl0, blo0 + ko); ldsm4(bl1, blo1 + ko);
        #pragma unroll
        for (int mi = 0; mi < 2; mi++) {
            const unsigned* ah = mi ? ah1 : ah0;
            const unsigned* al = mi ? al1 : al0;
            #pragma unroll
            for (int nb = 0; nb < 4; nb++) {
                const unsigned* bh = (nb < 2) ? bh0 : bh1;
                const unsigned* bl = (nb < 2) ? bl0 : bl1;
                const int ix = (nb & 1) * 2;
                mma16816(acc[mi][nb], ah, bh[ix], bh[ix + 1]);
                mma16816(acc[mi][nb], ah, bl[ix], bl[ix + 1]);
                mma16816(acc[mi][nb], al, bh[ix], bh[ix + 1]);
            }
        }
    }
    __syncthreads();

    float* rb = (float*)sm;
    #pragma unroll
    for (int mi = 0; mi < 2; mi++) {
        #pragma unroll
        for (int nb = 0; nb < 4; nb++) {
            int row = mg * 32 + mi * 16 + g8;
            int col = ngp * 32 + nb * 8 + 2 * t4;
            *(float2*)&rb[kg * RSLAB + row * RP + col]
                = make_float2(acc[mi][nb][0], acc[mi][nb][1]);
            *(float2*)&rb[kg * RSLAB + (row + 8) * RP + col]
                = make_float2(acc[mi][nb][2], acc[mi][nb][3]);
        }
    }
    __syncthreads();

    {
        const int g = ct >> 3;
        const float* bias = (g==0)?bf:(g==1)?bi:(g==2)?bc:bo;
        const int j0 = (ct & 7) * 64;
        const int r = t >> 2, cb = (t & 3) * 16;
        float* dst = &g_gx[((size_t)(st * 64 + r) * BB + b) * G4 + ct * 64 + cb];
        #pragma unroll
        for (int v4 = 0; v4 < 4; v4++) {
            float4 v;
            float* o = (float*)&v;
            #pragma unroll
            for (int q = 0; q < 4; q++) {
                int col = cb + v4 * 4 + q;
                o[q] = rb[r * RP + col] + rb[RSLAB + r * RP + col] + bias[j0 + col];
            }
            *(float4*)&dst[v4 * 4] = v;
        }
    }
}

// ---------------- persistent mma.sync step kernel (R12 + flag barrier) ----
__global__ void __launch_bounds__(256, 1) step_kernel() {
    extern __shared__ __align__(16) unsigned char sm[];
    const int cta = blockIdx.x, t = threadIdx.x;
    const int wid = t >> 5, lane = t & 31;
    const int g8 = lane >> 2, t4 = lane & 3;
    const int ng = wid & 1, kg = wid >> 1;
    const int n0 = ng * 32;

    {
        const uint4* shi = (const uint4*)g_whi[cta];
        const uint4* slo = (const uint4*)g_wlo[cta];
        #pragma unroll
        for (int i = 0; i < 8; i++) {
            int ch = i * 256 + t;
            int r = ch >> 6, cc = ch & 63;
            *(uint4*)(sm + SM_WHI + r * TPITCH + cc * 16) = shi[ch];
            *(uint4*)(sm + SM_WLO + r * TPITCH + cc * 16) = slo[ch];
        }
    }
    __syncthreads();

    const unsigned a_lr = (unsigned)((lane & 15) * TPITCH + ((lane & 16) ? 16 : 0));
    const unsigned ahi0 = smem_u32(sm + SM_WHI) + a_lr + (unsigned)(kg * 256);
    const unsigned ahi1 = ahi0 + 16u * TPITCH;
    const unsigned alo0 = ahi0 + (SM_WLO - SM_WHI);
    const unsigned alo1 = alo0 + 16u * TPITCH;
    const int brow = ((lane & 16) >> 1) + (lane & 7);
    const unsigned b_lr = (unsigned)(brow * TPITCH + ((lane & 8) ? 16 : 0));
    const unsigned bhi0 = smem_u32(sm + SM_HHI) + (unsigned)(n0 * TPITCH) + b_lr + (unsigned)(kg * 256);
    const unsigned bhi1 = bhi0 + 16u * TPITCH;
    const unsigned blo0 = bhi0 + (SM_HLO - SM_HHI);
    const unsigned blo1 = blo0 + 16u * TPITCH;

    const int ub = t >> 2, lp = (t & 3) * 2;
    float c_reg[2] = {};
    float* gb = (float*)(sm + SM_HHI);

    for (int s = 0; s < SS; s++) {
        const int par = s & 1;

        {
            const uint4* hs0 = (const uint4*)g_h[par][0];
            const uint4* hs1 = (const uint4*)g_h[par][1];
            #pragma unroll
            for (int i = 0; i < 16; i++) {
                int e = i * 32 + lane;
                int rr = e >> 4, cc = e & 15;
                int src = (n0 + rr) * 64 + kg * 16 + cc;
                unsigned dst = (unsigned)((n0 + rr) * TPITCH + kg * 256 + cc * 16);
                *(uint4*)(sm + SM_HHI + dst) = __ldcg(hs0 + src);
                *(uint4*)(sm + SM_HLO + dst) = __ldcg(hs1 + src);
            }
        }
        float2 gx[4];
        {
            const float* p = &g_gx[((size_t)s * BB + ub) * G4 + cta * 8 + lp];
            #pragma unroll
            for (int g = 0; g < 4; g++) gx[g] = *(const float2*)&p[g * 512];
        }
        __syncwarp();

        float acc[2][4][4] = {};
        #pragma unroll
        for (int kk = 0; kk < 8; kk++) {
            const unsigned ko = (unsigned)(kk * 32);
            unsigned ah0[4], ah1[4], al0[4], al1[4], bh0[4], bh1[4], bl0[4], bl1[4];
            ldsm4(ah0, ahi0 + ko); ldsm4(ah1, ahi1 + ko);
            ldsm4(al0, alo0 + ko); ldsm4(al1, alo1 + ko);
            ldsm4(bh0, bhi0 + ko); ldsm4(bh1, bhi1 + ko);
            ldsm4(bl0, blo0 + ko); ldsm4(bl1, blo1 + ko);
            #pragma unroll
            for (int mi = 0; mi < 2; mi++) {
                const unsigned* ah = mi ? ah1 : ah0;
                const unsigned* al = mi ? al1 : al0;
                #pragma unroll
                for (int nb = 0; nb < 4; nb++) {
                    const unsigned* bh = (nb < 2) ? bh0 : bh1;
                    const unsigned* bl = (nb < 2) ? bl0 : bl1;
                    const int ix = (nb & 1) * 2;
                    mma16816(acc[mi][nb], ah, bh[ix], bh[ix + 1]);
                    mma16816(acc[mi][nb], ah, bl[ix], bl[ix + 1]);
                    mma16816(acc[mi][nb], al, bh[ix], bh[ix + 1]);
                }
            }
        }
        __syncthreads();

        #pragma unroll
        for (int mi = 0; mi < 2; mi++) {
            #pragma unroll
            for (int nb = 0; nb < 4; nb++) {
                int row = kg * 32 + mi * 16 + g8;
                int col = n0 + nb * 8 + 2 * t4;
                *(float2*)&gb[row * GBP + col]       = make_float2(acc[mi][nb][0], acc[mi][nb][1]);
                *(float2*)&gb[(row + 8) * GBP + col] = make_float2(acc[mi][nb][2], acc[mi][nb][3]);
            }
        }
        __syncthreads();

        {
            float hv[2];
            #pragma unroll
            for (int q = 0; q < 2; q++) {
                int l = lp + q;
                float gsum[4];
                #pragma unroll
                for (int g = 0; g < 4; g++) {
                    float v = 0.f;
                    #pragma unroll
                    for (int k = 0; k < 4; k++)
                        v += gb[(k * 32 + g * 8 + l) * GBP + ub];
                    gsum[g] = v;
                }
                float gf = gsum[0] + ((q == 0) ? gx[0].x : gx[0].y);
                float gi = gsum[1] + ((q == 0) ? gx[1].x : gx[1].y);
                float gu = gsum[2] + ((q == 0) ? gx[2].x : gx[2].y);
                float go = gsum[3] + ((q == 0) ? gx[3].x : gx[3].y);
                float f = fsigmoid(gf), ii = fsigmoid(gi);
                float u = ftanh(gu),    o = fsigmoid(go);
                c_reg[q] = f * c_reg[q] + ii * u;
                hv[q] = o * ftanh(c_reg[q]);
            }
            __nv_bfloat16 h0 = __float2bfloat16(hv[0]);
            __nv_bfloat16 h1 = __float2bfloat16(hv[1]);
            unsigned hiw = (unsigned)__bfloat16_as_ushort(h0) | ((unsigned)__bfloat16_as_ushort(h1) << 16);
            unsigned low = bf2pack(hv[0] - __bfloat162float(h0), hv[1] - __bfloat162float(h1));
            const int j0 = cta * 8 + lp;
            *(unsigned*)&g_h[1 - par][0][ub * HH + j0] = hiw;
            *(unsigned*)&g_h[1 - par][1][ub * HH + j0] = low;
            if (s == SS - 1) {
                g_hfin[ub * HH + j0]     = hv[0];
                g_hfin[ub * HH + j0 + 1] = hv[1];
            }
        }

        // ---- chip barrier: 64 parallel flags; warp-0 spin with backoff ----
        __syncthreads();                 // all h writes of this CTA done
        if (t == 0) {
            __threadfence();             // publish h at gpu scope
            asm volatile("st.release.gpu.u32 [%0], %1;"
                         :: "l"(&g_flags[cta * FLAG_PAD]), "r"((unsigned)(s + 1))
                         : "memory");
        }
        if (t < 32) {
            #pragma unroll
            for (int half = 0; half < 2; half++) {
                const unsigned* fp = &g_flags[(t + half * 32) * FLAG_PAD];
                unsigned v;
                asm volatile("ld.acquire.gpu.u32 %0, [%1];" : "=r"(v) : "l"(fp) : "memory");
                while (v < (unsigned)(s + 1)) {
                    asm volatile("nanosleep.u32 64;");
                    asm volatile("ld.acquire.gpu.u32 %0, [%1];" : "=r"(v) : "l"(fp) : "memory");
                }
            }
        }
        __syncthreads();                 // all flags seen -> safe to read h
    }
}

// ---------------- output head ----------------
__global__ void __launch_bounds__(256) out_kernel(
    const float* __restrict__ Wout, const float* __restrict__ bout,
    float* __restrict__ out)
{
    __shared__ float hsh[HH];
    const int b = blockIdx.x, j = threadIdx.x;
    for (int k = j; k < HH; k += 256) hsh[k] = g_hfin[b * HH + k];
    __syncthreads();
    float a0 = 0.f, a1 = 0.f, a2 = 0.f, a3 = 0.f;
    #pragma unroll 4
    for (int k = 0; k < HH; k += 4) {
        a0 += hsh[k+0] * Wout[(size_t)(k+0)*OO + j];
        a1 += hsh[k+1] * Wout[(size_t)(k+1)*OO + j];
        a2 += hsh[k+2] * Wout[(size_t)(k+2)*OO + j];
        a3 += hsh[k+3] * Wout[(size_t)(k+3)*OO + j];
    }
    out[(size_t)b * OO + j] = a0 + a1 + a2 + a3 + bout[j];
}

// ---------------- launcher ----------------
extern "C" void kernel_launch(void* const* d_in, const int* in_sizes, int n_in,
                              void* d_out, int out_size)
{
    (void)in_sizes; (void)n_in; (void)out_size;
    const float* x    = (const float*)d_in[0];
    const float* Wf   = (const float*)d_in[1];
    const float* bf   = (const float*)d_in[2];
    const float* Wi   = (const float*)d_in[3];
    const float* bi   = (const float*)d_in[4];
    const float* Wc   = (const float*)d_in[5];
    const float* bc   = (const float*)d_in[6];
    const float* Wo   = (const float*)d_in[7];
    const float* bo   = (const float*)d_in[8];
    const float* Wout = (const float*)d_in[9];
    const float* bout = (const float*)d_in[10];
    float* out = (float*)d_out;

    cudaFuncSetAttribute(step_kernel,
                         cudaFuncAttributeMaxDynamicSharedMemorySize, SM_TOTAL);
    cudaFuncSetAttribute(precompute2_kernel,
                         cudaFuncAttributeMaxDynamicSharedMemorySize, PC_TOTAL);

    init_kernel<<<128, 256>>>();
    prepw_kernel<<<2048, 256>>>(Wf, Wi, Wc, Wo);
    prepx_kernel<<<16384, 256>>>(x);
    prepwx_kernel<<<1024, 256>>>(Wf, Wi, Wc, Wo);
    precompute2_kernel<<<dim3(32, 16, BB), 256, PC_TOTAL>>>(bf, bi, bc, bo);
    step_kernel<<<NCTA, 256, SM_TOTAL>>>();
    out_kernel<<<BB, 256>>>(Wout, bout, out);
}